// round 2
// baseline (speedup 1.0000x reference)
#include <cuda_runtime.h>
#include <cuda_bf16.h>

// Scratch: device-global accumulator (no allocations allowed).
__device__ float g_accum;

__global__ void wmse_init_kernel() {
    g_accum = 0.0f;
}

__global__ void __launch_bounds__(256) wmse_reduce_kernel(
    const float4* __restrict__ pred4,
    const int4*  __restrict__ lab4,
    const float* __restrict__ weights,
    long long nvec)
{
    __shared__ float sw[16];
    if (threadIdx.x < 10) sw[threadIdx.x] = weights[threadIdx.x];
    __syncthreads();

    float acc = 0.0f;
    long long i = (long long)blockIdx.x * blockDim.x + threadIdx.x;
    const long long stride = (long long)gridDim.x * blockDim.x;

    // Grid-stride over float4/int4 vectors. Two LDG.128 per iteration,
    // unrolled 2x by the compiler gives 4 outstanding 16B loads per thread.
    #pragma unroll 2
    for (; i < nvec; i += stride) {
        float4 p = pred4[i];
        int4   l = lab4[i];
        float d0 = p.x - (float)l.x;
        float d1 = p.y - (float)l.y;
        float d2 = p.z - (float)l.z;
        float d3 = p.w - (float)l.w;
        acc = fmaf(sw[l.x] * d0, d0, acc);
        acc = fmaf(sw[l.y] * d1, d1, acc);
        acc = fmaf(sw[l.z] * d2, d2, acc);
        acc = fmaf(sw[l.w] * d3, d3, acc);
    }

    // Warp reduction
    #pragma unroll
    for (int off = 16; off > 0; off >>= 1)
        acc += __shfl_down_sync(0xFFFFFFFFu, acc, off);

    __shared__ float warp_sums[8];
    int warp = threadIdx.x >> 5;
    int lane = threadIdx.x & 31;
    if (lane == 0) warp_sums[warp] = acc;
    __syncthreads();

    if (warp == 0) {
        acc = (lane < 8) ? warp_sums[lane] : 0.0f;
        #pragma unroll
        for (int off = 4; off > 0; off >>= 1)
            acc += __shfl_down_sync(0xFFFFFFFFu, acc, off);
        if (lane == 0)
            atomicAdd(&g_accum, acc);
    }
}

__global__ void wmse_finalize_kernel(float* __restrict__ out, float inv_n) {
    out[0] = g_accum * inv_n;
}

extern "C" void kernel_launch(void* const* d_in, const int* in_sizes, int n_in,
                              void* d_out, int out_size) {
    const float* predictions = (const float*)d_in[0];
    const int*   labels      = (const int*)d_in[1];
    const float* weights     = (const float*)d_in[2];
    float*       out         = (float*)d_out;

    const long long n = (long long)in_sizes[0];      // 33,554,432 (divisible by 4)
    const long long nvec = n >> 2;

    wmse_init_kernel<<<1, 1>>>();

    const int block = 256;
    // ~8192 blocks: each thread handles 16 vec4 elements via grid-stride.
    int grid = (int)((nvec + (long long)block * 16 - 1) / ((long long)block * 16));
    if (grid < 1) grid = 1;
    wmse_reduce_kernel<<<grid, block>>>(
        (const float4*)predictions, (const int4*)labels, weights, nvec);

    wmse_finalize_kernel<<<1, 1>>>(out, 1.0f / (float)n);
}